// round 13
// baseline (speedup 1.0000x reference)
#include <cuda_runtime.h>
#include <cuda_bf16.h>

// PrototypeLoss: out = mean_i ||features[i] - prototypes[labels[i]]||^2
// N=131072, D=512, C=1000.
//
// R11 gather version sits at the LTS throughput cap (~11.3 TB/s: 268MB feature
// DRAM stream + 268MB prototype L2-hit stream). This version counting-sorts
// row ids by label with a lean 3-launch pre-pass (labels are only 0.5MB),
// then streams features with the class prototype held in REGISTERS ->
// prototype L2 traffic ~2MB, LTS carries only the feature stream.
//
// inputs identified by element count:
//   features f32 [N,D]=67108864, labels int [N]=131072 (dtype sniffed),
//   protos f32 [C,D]=512000.  output: f32 [1,1]

#define N_ROWS 131072
#define NC 1000
#define D_VEC 128                    // D/4 float4 per row
#define HB 148                       // hist/scatter blocks
#define CHUNK ((N_ROWS + HB - 1) / HB)   // 886 labels per block
#define MAIN_BLOCKS (2 * NC)         // two half-classes per class
#define BT 256

__device__ int      g_hist_pb[HB * NC];   // [b][c]; scan converts counts->starts
__device__ int      g_off[NC + 1];
__device__ int      g_rows[N_ROWS];
__device__ int      g_is64;
__device__ double   g_bpart[MAIN_BLOCKS];
__device__ unsigned g_done;               // zero at load; reset by last block

// int64 labels in [0,1000) -> odd 32-bit words of first 64 entries all zero.
// For int32 that needs 64 specific labels == 0 (p ~ 1e-192).
__device__ __forceinline__ int sniff_is64(const unsigned* lw, int lane) {
    unsigned w = lw[2 * lane + 1] | lw[2 * lane + 65];
    #pragma unroll
    for (int off = 16; off; off >>= 1)
        w |= __shfl_xor_sync(0xFFFFFFFFu, w, off);
    return (w == 0u) ? 1 : 0;
}

__device__ __forceinline__ int load_label(const void* lr, int i, int is64) {
    int l = is64 ? (int)((const long long*)lr)[i] : ((const int*)lr)[i];
    return (l < 0) ? 0 : (l >= NC ? NC - 1 : l);
}

// ---------- K1: per-block histogram (no atomics in gmem, no zero pass) ------
__global__ __launch_bounds__(BT)
void presort_kernel(const void* __restrict__ labels_raw) {
    __shared__ int sh[NC];
    __shared__ int s_is64;
    const int lane = threadIdx.x & 31;
    if (threadIdx.x < 32) {
        int v = sniff_is64((const unsigned*)labels_raw, lane);
        if (lane == 0) s_is64 = v;
    }
    for (int i = threadIdx.x; i < NC; i += BT) sh[i] = 0;
    __syncthreads();
    const int is64 = s_is64;
    const int beg = blockIdx.x * CHUNK;
    const int end = min(beg + CHUNK, N_ROWS);
    for (int i = beg + threadIdx.x; i < end; i += BT)
        atomicAdd(&sh[load_label(labels_raw, i, is64)], 1);
    __syncthreads();
    for (int c = threadIdx.x; c < NC; c += BT)
        g_hist_pb[blockIdx.x * NC + c] = sh[c];
    if (blockIdx.x == 0 && threadIdx.x == 0) g_is64 = is64;
}

// ---------- K2: column totals + class scan + per-(b,c) starts ---------------
__global__ __launch_bounds__(1024)
void scan_kernel() {
    __shared__ int s[1024];
    const int c = threadIdx.x;
    int total = 0;
    if (c < NC)
        for (int b = 0; b < HB; b++) total += g_hist_pb[b * NC + c];  // coalesced
    s[c] = (c < NC) ? total : 0;
    __syncthreads();
    #pragma unroll
    for (int off = 1; off < 1024; off <<= 1) {
        int x = (c >= off) ? s[c - off] : 0;
        __syncthreads();
        s[c] += x;
        __syncthreads();
    }
    if (c < NC) {
        int run = s[c] - total;         // exclusive class start
        g_off[c] = run;
        for (int b = 0; b < HB; b++) {  // convert counts -> scatter starts
            int t = g_hist_pb[b * NC + c];
            g_hist_pb[b * NC + c] = run;
            run += t;
        }
    }
    if (c == 0) g_off[NC] = N_ROWS;
}

// ---------- K3: scatter row ids (smem cursors, smem atomics) ----------------
__global__ __launch_bounds__(BT)
void scatter_kernel(const void* __restrict__ labels_raw) {
    __shared__ int cur[NC];
    for (int c = threadIdx.x; c < NC; c += BT)
        cur[c] = g_hist_pb[blockIdx.x * NC + c];
    __syncthreads();
    const int is64 = g_is64;
    const int beg = blockIdx.x * CHUNK;
    const int end = min(beg + CHUNK, N_ROWS);
    for (int i = beg + threadIdx.x; i < end; i += BT) {
        const int c = load_label(labels_raw, i, is64);
        const int pos = atomicAdd(&cur[c], 1);
        g_rows[pos] = i;
    }
}

// ---------- K4: per-half-class distance + fused final reduce ----------------
__device__ __forceinline__ float row_dist_reg(const float4* __restrict__ f,
                                              const float4 pv[4], int lane) {
    float acc = 0.0f;
    #pragma unroll
    for (int j = 0; j < 4; j++) {
        float4 a = f[lane + j * 32];
        float dx = a.x - pv[j].x;
        float dy = a.y - pv[j].y;
        float dz = a.z - pv[j].z;
        float dw = a.w - pv[j].w;
        acc = fmaf(dx, dx, acc);
        acc = fmaf(dy, dy, acc);
        acc = fmaf(dz, dz, acc);
        acc = fmaf(dw, dw, acc);
    }
    return acc;
}

#define STAGE 256   // rows staged to smem per pass (half-class avg ~66)

__global__ __launch_bounds__(BT, 6)
void main_kernel(const float4* __restrict__ feat,
                 const float4* __restrict__ protos,
                 float* __restrict__ out) {
    const int c    = blockIdx.x >> 1;
    const int half = blockIdx.x & 1;
    const int lane = threadIdx.x & 31;
    const int wid  = threadIdx.x >> 5;

    const int cs = g_off[c];
    const int ce = g_off[c + 1];
    const int mid = cs + ((ce - cs + 1) >> 1);
    int beg = half ? mid : cs;
    int end = half ? ce  : mid;

    // Prototype resident in registers for the whole block.
    float4 pv[4];
    #pragma unroll
    for (int j = 0; j < 4; j++)
        pv[j] = __ldg(&protos[(size_t)c * D_VEC + lane + j * 32]);

    __shared__ int   sidx[STAGE];
    __shared__ float ssum[BT / 32];
    __shared__ int   s_last;

    float acc = 0.0f;
    for (int base = beg; base < end; base += STAGE) {
        const int cnt = min(STAGE, end - base);
        // coalesced stage of row ids into smem (kills index->feature chain)
        for (int i = threadIdx.x; i < cnt; i += BT)
            sidx[i] = g_rows[base + i];
        __syncthreads();
        // 8 warps stride the staged list, 2 rows in flight each
        for (int t = wid; t < cnt; t += 16) {
            const float4* f0 = feat + (size_t)sidx[t] * D_VEC;
            if (t + 8 < cnt) {
                const float4* f1 = feat + (size_t)sidx[t + 8] * D_VEC;
                acc += row_dist_reg(f0, pv, lane);
                acc += row_dist_reg(f1, pv, lane);
            } else {
                acc += row_dist_reg(f0, pv, lane);
            }
        }
        __syncthreads();
    }

    #pragma unroll
    for (int off = 16; off; off >>= 1)
        acc += __shfl_xor_sync(0xFFFFFFFFu, acc, off);
    if (lane == 0) ssum[wid] = acc;
    __syncthreads();

    if (wid == 0) {
        float v = (lane < (BT / 32)) ? ssum[lane] : 0.0f;
        #pragma unroll
        for (int off = 4; off; off >>= 1)
            v += __shfl_xor_sync(0xFFFFFFFFu, v, off);
        if (lane == 0) {
            g_bpart[blockIdx.x] = (double)v;
            __threadfence();
            unsigned ticket = atomicAdd(&g_done, 1u);
            s_last = (ticket == MAIN_BLOCKS - 1) ? 1 : 0;
        }
    }
    __syncthreads();

    if (s_last) {
        __threadfence();
        __shared__ double dsum[BT / 32];
        double d = 0.0;
        for (int i = threadIdx.x; i < MAIN_BLOCKS; i += BT)
            d += g_bpart[i];
        #pragma unroll
        for (int off = 16; off; off >>= 1)
            d += __shfl_xor_sync(0xFFFFFFFFu, d, off);
        if (lane == 0) dsum[wid] = d;
        __syncthreads();
        if (wid == 0) {
            double t = (lane < (BT / 32)) ? dsum[lane] : 0.0;
            #pragma unroll
            for (int off = 4; off; off >>= 1)
                t += __shfl_xor_sync(0xFFFFFFFFu, t, off);
            if (lane == 0) {
                out[0] = (float)(t * (1.0 / (double)N_ROWS));
                g_done = 0u;   // clean state for next graph replay
            }
        }
    }
}

extern "C" void kernel_launch(void* const* d_in, const int* in_sizes, int n_in,
                              void* d_out, int out_size) {
    const float4* feat   = 0;
    const void*   labels = 0;
    const float4* protos = 0;
    for (int i = 0; i < n_in; i++) {
        if (in_sizes[i] == N_ROWS * 512)      feat   = (const float4*)d_in[i];
        else if (in_sizes[i] == NC * 512)     protos = (const float4*)d_in[i];
        else                                  labels = d_in[i];
    }
    float* out = (float*)d_out;

    presort_kernel<<<HB, BT>>>(labels);
    scan_kernel<<<1, 1024>>>();
    scatter_kernel<<<HB, BT>>>(labels);
    main_kernel<<<MAIN_BLOCKS, BT>>>(feat, protos, out);
}

// round 15
// speedup vs baseline: 1.9032x; 1.9032x over previous
#include <cuda_runtime.h>
#include <cuda_bf16.h>

// PrototypeLoss: out = mean_i ||features[i] - prototypes[labels[i]]||^2
// N=131072, D=512, C=1000. Pure HBM-streaming gather-reduction (~257 MB).
//
// R13 lesson: counting-sort + registered prototypes LOST (random feature
// access, 54% DRAM). Sequential gather (R11, 72.8% DRAM, latency-exposed)
// is the right architecture; this round raises occupancy 48->64 warps/SM
// (launch_bounds(256,8), 32-reg cap) to close the latency gap.
//
// inputs identified by element count:
//   features f32 [N,D]=67108864, labels int [N]=131072 (dtype sniffed),
//   protos f32 [C,D]=512000.  output: f32 [1,1]

#define N_ROWS 131072
#define N_CLASSES 1000
#define D_VEC  128                 // D/4 float4 per row
#define BLOCKS_PER_SM 8
#define GRID_BLOCKS (148 * BLOCKS_PER_SM)   // 1184 = one full wave
#define BLOCK_THREADS 256
#define WARPS_TOTAL ((GRID_BLOCKS * BLOCK_THREADS) >> 5)          // 9472
#define MAX_ITERS ((N_ROWS + WARPS_TOTAL - 1) / WARPS_TOTAL)      // 14

__device__ float    g_partials[GRID_BLOCKS];
__device__ unsigned g_done;   // zero-init at load; reset by last block each run

__device__ __forceinline__ float row_dist_partial(const float4* __restrict__ f,
                                                  const float4* __restrict__ p,
                                                  int lane) {
    float acc = 0.0f;
    #pragma unroll
    for (int j = 0; j < 4; j++) {
        const int idx = lane + j * 32;
        float4 a = f[idx];
        float4 b = p[idx];
        float dx = a.x - b.x;
        float dy = a.y - b.y;
        float dz = a.z - b.z;
        float dw = a.w - b.w;
        acc = fmaf(dx, dx, acc);
        acc = fmaf(dy, dy, acc);
        acc = fmaf(dz, dz, acc);
        acc = fmaf(dw, dw, acc);
    }
    return acc;
}

__global__ __launch_bounds__(BLOCK_THREADS, BLOCKS_PER_SM)
void proto_loss_kernel(const float4* __restrict__ feat,
                       const void* __restrict__ labels_raw,
                       const float4* __restrict__ protos,
                       float* __restrict__ out) {
    const int lane = threadIdx.x & 31;
    const int wid  = threadIdx.x >> 5;

    __shared__ int   s_is64;
    __shared__ float ssum[BLOCK_THREADS / 32];
    __shared__ int   s_last;

    // --- Label dtype sniff (warp 0): for int64 labels in [0,1000), the odd
    // 32-bit words of the first 64 entries are all zero. For int32 that needs
    // 64 specific labels == 0 (p ~ 1e-192). Words 1..128 stay within N*4
    // bytes for either dtype.
    if (wid == 0) {
        const unsigned* lw = (const unsigned*)labels_raw;
        unsigned w = lw[2 * lane + 1] | lw[2 * lane + 65];
        #pragma unroll
        for (int off = 16; off; off >>= 1)
            w |= __shfl_xor_sync(0xFFFFFFFFu, w, off);
        if (lane == 0) s_is64 = (w == 0u) ? 1 : 0;
    }
    __syncthreads();
    const int is64 = s_is64;
    const int*       l32 = (const int*)labels_raw;
    const long long* l64 = (const long long*)labels_raw;

    const int gwarp = (blockIdx.x * BLOCK_THREADS + threadIdx.x) >> 5;

    // --- Preload this warp's labels: lane k holds the label for iteration k
    // (MAX_ITERS=14 <= 32). Removes the label load and its load->gather
    // dependency from the hot loop.
    int mylbl = 0;
    {
        const int myrow = gwarp + lane * WARPS_TOTAL;
        if (lane < MAX_ITERS && myrow < N_ROWS) {
            int l = is64 ? (int)l64[myrow] : l32[myrow];
            mylbl = (l < 0) ? 0 : (l >= N_CLASSES ? N_CLASSES - 1 : l);
        }
    }

    float acc = 0.0f;

    // One row per iteration (8 batched float4 loads); labels from shfl.
    // 64 warps/SM provide the memory-level parallelism.
    #pragma unroll
    for (int it = 0; it < MAX_ITERS; it++) {
        const int row = gwarp + it * WARPS_TOTAL;
        const int lbl = __shfl_sync(0xFFFFFFFFu, mylbl, it);
        if (row < N_ROWS) {
            const float4* f = feat   + (size_t)row * D_VEC;
            const float4* p = protos + (size_t)lbl * D_VEC;
            acc += row_dist_partial(f, p, lane);
        }
    }

    // warp reduce
    #pragma unroll
    for (int off = 16; off; off >>= 1)
        acc += __shfl_xor_sync(0xFFFFFFFFu, acc, off);
    if (lane == 0) ssum[wid] = acc;
    __syncthreads();

    // block reduce + publish partial; last block to arrive finishes.
    if (wid == 0) {
        float v = (lane < (BLOCK_THREADS / 32)) ? ssum[lane] : 0.0f;
        #pragma unroll
        for (int off = 4; off; off >>= 1)
            v += __shfl_xor_sync(0xFFFFFFFFu, v, off);
        if (lane == 0) {
            g_partials[blockIdx.x] = v;
            __threadfence();
            unsigned ticket = atomicAdd(&g_done, 1u);
            s_last = (ticket == GRID_BLOCKS - 1) ? 1 : 0;
        }
    }
    __syncthreads();

    if (s_last) {
        __threadfence();  // all g_partials writes visible
        __shared__ double dsum[BLOCK_THREADS / 32];
        double d = 0.0;
        for (int i = threadIdx.x; i < GRID_BLOCKS; i += BLOCK_THREADS)
            d += (double)g_partials[i];
        #pragma unroll
        for (int off = 16; off; off >>= 1)
            d += __shfl_xor_sync(0xFFFFFFFFu, d, off);
        if (lane == 0) dsum[wid] = d;
        __syncthreads();
        if (wid == 0) {
            double t = (lane < (BLOCK_THREADS / 32)) ? dsum[lane] : 0.0;
            #pragma unroll
            for (int off = 4; off; off >>= 1)
                t += __shfl_xor_sync(0xFFFFFFFFu, t, off);
            if (lane == 0) {
                out[0] = (float)(t * (1.0 / (double)N_ROWS));
                g_done = 0u;   // reset for next graph replay
            }
        }
    }
}

extern "C" void kernel_launch(void* const* d_in, const int* in_sizes, int n_in,
                              void* d_out, int out_size) {
    const float4* feat   = 0;
    const void*   labels = 0;
    const float4* protos = 0;
    for (int i = 0; i < n_in; i++) {
        if (in_sizes[i] == N_ROWS * 512)          feat   = (const float4*)d_in[i];
        else if (in_sizes[i] == N_CLASSES * 512)  protos = (const float4*)d_in[i];
        else                                      labels = d_in[i];
    }
    float* out = (float*)d_out;

    proto_loss_kernel<<<GRID_BLOCKS, BLOCK_THREADS>>>(feat, labels, protos, out);
}